// round 3
// baseline (speedup 1.0000x reference)
#include <cuda_runtime.h>
#include <math.h>
#include <float.h>

// ============================================================================
// HybridViT forward: CNN patch embed (3x [conv7s2 + relu + maxpool7s1p1])
// -> flatten linear -> +cls +pos -> 6x transformer layer -> LN -> head.
// All fp32. Round 1: fp32 FMA-bound tiled direct convs, separable pools,
// tiled SGEMM for all dense layers, one-block-per-(b,h) attention.
// ============================================================================

#define NPATCH 256      // B*NP = 16*16
#define ROWS   272      // B*(NP+1) = 16*17

// ---------------- scratch (device globals; allocation-free rule) ------------
__device__ float g_patches[(size_t)NPATCH*220*220];
__device__ float g_c1[(size_t)NPATCH*32*107*107];
__device__ float g_t1[(size_t)NPATCH*32*107*103];
__device__ float g_p1[(size_t)NPATCH*32*103*103];
__device__ float g_c2[(size_t)NPATCH*64*49*49];
__device__ float g_t2[(size_t)NPATCH*64*49*45];
__device__ float g_p2[(size_t)NPATCH*64*45*45];
__device__ float g_c3[(size_t)NPATCH*64*20*20];
__device__ float g_t3[(size_t)NPATCH*64*20*16];
__device__ float g_p3[(size_t)NPATCH*64*16*16];   // == feat [256, 16384]
__device__ float g_tok[(size_t)NPATCH*512];
__device__ float g_x  [(size_t)ROWS*512];
__device__ float g_h  [(size_t)ROWS*512];
__device__ float g_qkv[(size_t)ROWS*1536];
__device__ float g_o  [(size_t)ROWS*512];
__device__ float g_ff [(size_t)ROWS*2048];
__device__ float g_cls[(size_t)16*512];

// ---------------- patch extraction -----------------------------------------
__global__ void extract_patches_kernel(const float* __restrict__ img)
{
    int idx = blockIdx.x * blockDim.x + threadIdx.x;
    const int PER = 220 * 220;
    if (idx >= NPATCH * PER) return;
    int p   = idx / PER;
    int rem = idx - p * PER;
    int iy = rem / 220, ix = rem - (rem / 220) * 220;
    int b  = p >> 4;
    int gh = (p >> 2) & 3;
    int gw = p & 3;
    g_patches[idx] = img[((size_t)(b * 880 + gh * 220 + iy)) * 880 + gw * 220 + ix];
}

// ---------------- direct conv 7x7 stride 2 VALID + ReLU ---------------------
// block: one patch x one 8x8 output tile x all OC channels.
// thread: 4 oc x 4 positions (16 FMA per 8 LDS per k-step -> FMA-bound).
template<int IC, int OC, int IN_H, int IN_W, int OUT_H, int OUT_W>
__global__ void conv7s2_relu_kernel(const float* __restrict__ in,
                                    const float* __restrict__ w,
                                    float* __restrict__ out)
{
    constexpr int TH = 8, TW = 8;
    constexpr int ITH = 21, ITW = 21;           // (8-1)*2+7
    constexpr int NT  = (OC / 4) * 16;
    __shared__ float s_w[OC * 49];
    __shared__ float s_in[ITH * ITW];
    const int patch = blockIdx.x;
    constexpr int TILES_W = (OUT_W + TW - 1) / TW;
    const int oy0 = (blockIdx.y / TILES_W) * TH;
    const int ox0 = (blockIdx.y % TILES_W) * TW;
    const int t   = threadIdx.x;
    const int oc0 = (t % (OC / 4)) * 4;
    const int pg  = t / (OC / 4);               // 0..15
    int py[4], px[4];
#pragma unroll
    for (int j = 0; j < 4; j++) { int p = pg * 4 + j; py[j] = p >> 3; px[j] = p & 7; }
    float acc[4][4];
#pragma unroll
    for (int i = 0; i < 4; i++)
#pragma unroll
        for (int j = 0; j < 4; j++) acc[i][j] = 0.f;

    const float* in_p = in + (size_t)patch * IC * IN_H * IN_W;
    for (int ci = 0; ci < IC; ci++) {
        __syncthreads();
        for (int idx = t; idx < OC * 49; idx += NT) {
            int oc = idx / 49, k = idx - oc * 49;
            s_w[idx] = w[((size_t)oc * IC + ci) * 49 + k];
        }
        const float* in_c = in_p + (size_t)ci * IN_H * IN_W;
        for (int idx = t; idx < ITH * ITW; idx += NT) {
            int ly = idx / ITW, lx = idx - ly * ITW;
            int iy = oy0 * 2 + ly, ix = ox0 * 2 + lx;
            s_in[idx] = (iy < IN_H && ix < IN_W) ? in_c[(size_t)iy * IN_W + ix] : 0.f;
        }
        __syncthreads();
#pragma unroll
        for (int kh = 0; kh < 7; kh++) {
#pragma unroll
            for (int kw = 0; kw < 7; kw++) {
                const int k = kh * 7 + kw;
                float wr[4], vr[4];
#pragma unroll
                for (int i = 0; i < 4; i++) wr[i] = s_w[(oc0 + i) * 49 + k];
#pragma unroll
                for (int j = 0; j < 4; j++) vr[j] = s_in[(py[j] * 2 + kh) * ITW + (px[j] * 2 + kw)];
#pragma unroll
                for (int i = 0; i < 4; i++)
#pragma unroll
                    for (int j = 0; j < 4; j++) acc[i][j] = fmaf(wr[i], vr[j], acc[i][j]);
            }
        }
    }
#pragma unroll
    for (int i = 0; i < 4; i++) {
        const int oc = oc0 + i;
#pragma unroll
        for (int j = 0; j < 4; j++) {
            int oy = oy0 + py[j], ox = ox0 + px[j];
            if (oy < OUT_H && ox < OUT_W)
                out[(((size_t)patch * OC + oc) * OUT_H + oy) * OUT_W + ox] = fmaxf(acc[i][j], 0.f);
        }
    }
}

// ---------------- separable maxpool 7x7 stride1 pad1 ------------------------
template<int W, int OW>
__global__ void pool_cols_kernel(const float* __restrict__ in, float* __restrict__ out, int rows)
{
    int idx = blockIdx.x * blockDim.x + threadIdx.x;
    if (idx >= rows * OW) return;
    int r = idx / OW, ox = idx - r * OW;
    const float* p = in + (size_t)r * W;
    int lo = ox - 1 < 0 ? 0 : ox - 1;
    int hi = ox + 5 > W - 1 ? W - 1 : ox + 5;
    float m = -FLT_MAX;
    for (int ix = lo; ix <= hi; ix++) m = fmaxf(m, p[ix]);
    out[(size_t)r * OW + ox] = m;
}

template<int H, int OH, int OW>
__global__ void pool_rows_kernel(const float* __restrict__ in, float* __restrict__ out, int planes)
{
    int idx = blockIdx.x * blockDim.x + threadIdx.x;
    if (idx >= planes * OH * OW) return;
    int pl  = idx / (OH * OW);
    int rem = idx - pl * (OH * OW);
    int oy = rem / OW, ox = rem - oy * OW;
    int lo = oy - 1 < 0 ? 0 : oy - 1;
    int hi = oy + 5 > H - 1 ? H - 1 : oy + 5;
    const float* p = in + (size_t)pl * H * OW;
    float m = -FLT_MAX;
    for (int iy = lo; iy <= hi; iy++) m = fmaxf(m, p[(size_t)iy * OW + ox]);
    out[idx] = m;
}

// ---------------- tiled SGEMM: C = act(A@B + bias) + res --------------------
__device__ __forceinline__ float gelu_f(float x)
{
    return 0.5f * x * (1.0f + erff(x * 0.7071067811865476f));
}

template<int ACT>   // 0 = none, 1 = exact GELU (applied before residual)
__global__ void gemm_kernel(const float* __restrict__ A, const float* __restrict__ Bm,
                            const float* __restrict__ bias, const float* __restrict__ res,
                            float* __restrict__ C, int M, int N, int K)
{
    __shared__ float sA[16][33];
    __shared__ float sB[16][64];
    const int bm = blockIdx.y * 32;
    const int bn = blockIdx.x * 64;
    const int t  = threadIdx.x;          // 256
    const int tm = (t >> 4) << 1;        // 0..30
    const int tn = (t & 15) << 2;        // 0..60
    float acc[2][4] = {{0, 0, 0, 0}, {0, 0, 0, 0}};
    for (int k0 = 0; k0 < K; k0 += 16) {
#pragma unroll
        for (int i = 0; i < 2; i++) {
            int e = t * 2 + i, m = e >> 4, kk = e & 15;
            sA[kk][m] = (bm + m < M) ? A[(size_t)(bm + m) * K + k0 + kk] : 0.f;
        }
#pragma unroll
        for (int i = 0; i < 4; i++) {
            int e = t * 4 + i, kk = e >> 6, n = e & 63;
            sB[kk][n] = (bn + n < N) ? Bm[(size_t)(k0 + kk) * N + bn + n] : 0.f;
        }
        __syncthreads();
#pragma unroll
        for (int kk = 0; kk < 16; kk++) {
            float a0 = sA[kk][tm], a1 = sA[kk][tm + 1];
            float b0 = sB[kk][tn + 0], b1 = sB[kk][tn + 1];
            float b2 = sB[kk][tn + 2], b3 = sB[kk][tn + 3];
            acc[0][0] = fmaf(a0, b0, acc[0][0]); acc[0][1] = fmaf(a0, b1, acc[0][1]);
            acc[0][2] = fmaf(a0, b2, acc[0][2]); acc[0][3] = fmaf(a0, b3, acc[0][3]);
            acc[1][0] = fmaf(a1, b0, acc[1][0]); acc[1][1] = fmaf(a1, b1, acc[1][1]);
            acc[1][2] = fmaf(a1, b2, acc[1][2]); acc[1][3] = fmaf(a1, b3, acc[1][3]);
        }
        __syncthreads();
    }
#pragma unroll
    for (int i = 0; i < 2; i++) {
        int m = bm + tm + i;
        if (m >= M) continue;
#pragma unroll
        for (int j = 0; j < 4; j++) {
            int n = bn + tn + j;
            if (n >= N) continue;
            float v = acc[i][j];
            if (bias) v += bias[n];
            if (ACT == 1) v = gelu_f(v);
            if (res) v += res[(size_t)m * N + n];
            C[(size_t)m * N + n] = v;
        }
    }
}

// ---------------- LayerNorm over 512 ----------------------------------------
__global__ void ln_kernel(const float* __restrict__ x, const float* __restrict__ g,
                          const float* __restrict__ bb, float* __restrict__ out,
                          int row_stride)
{
    const int row = blockIdx.x;
    const float* xr = x + (size_t)row * row_stride;
    float* orow = out + (size_t)row * 512;
    const int t = threadIdx.x; // 128
    float v[4], s = 0.f, s2 = 0.f;
#pragma unroll
    for (int i = 0; i < 4; i++) { v[i] = xr[i * 128 + t]; s += v[i]; s2 += v[i] * v[i]; }
#pragma unroll
    for (int o = 16; o; o >>= 1) {
        s  += __shfl_xor_sync(0xffffffffu, s,  o);
        s2 += __shfl_xor_sync(0xffffffffu, s2, o);
    }
    __shared__ float rs[4], rs2[4];
    if ((t & 31) == 0) { rs[t >> 5] = s; rs2[t >> 5] = s2; }
    __syncthreads();
    float tot  = rs[0] + rs[1] + rs[2] + rs[3];
    float tot2 = rs2[0] + rs2[1] + rs2[2] + rs2[3];
    float mean = tot  * (1.f / 512.f);
    float var  = tot2 * (1.f / 512.f) - mean * mean;
    float rstd = rsqrtf(var + 1e-5f);
#pragma unroll
    for (int i = 0; i < 4; i++) {
        int c = i * 128 + t;
        orow[c] = (v[i] - mean) * rstd * g[c] + bb[c];
    }
}

// ---------------- token assembly: cls + tokens + pos ------------------------
__global__ void embed_kernel(const float* __restrict__ cls_token, const float* __restrict__ pos_emb)
{
    int idx = blockIdx.x * blockDim.x + threadIdx.x;
    if (idx >= ROWS * 512) return;
    int row = idx >> 9, c = idx & 511;
    int b = row / 17, n = row - b * 17;
    float v = (n == 0) ? cls_token[c] : g_tok[(size_t)(b * 16 + n - 1) * 512 + c];
    g_x[idx] = v + pos_emb[n * 512 + c];
}

// ---------------- attention: one block per (b, h), N=17, DH=64 --------------
__global__ void attn_kernel()
{
    const int bh = blockIdx.x;
    const int b = bh >> 3, h = bh & 7;
    __shared__ float q[17][64], kk[17][64], vv[17][64], s[17][17];
    const int t = threadIdx.x; // 128
    for (int idx = t; idx < 17 * 64; idx += 128) {
        int n = idx >> 6, d = idx & 63;
        const float* base = g_qkv + (size_t)(b * 17 + n) * 1536 + h * 64 + d;
        q[n][d]  = base[0];
        kk[n][d] = base[512];
        vv[n][d] = base[1024];
    }
    __syncthreads();
    for (int idx = t; idx < 289; idx += 128) {
        int i = idx / 17, j = idx - i * 17;
        float a = 0.f;
#pragma unroll
        for (int d = 0; d < 64; d++) a = fmaf(q[i][d], kk[j][d], a);
        s[i][j] = a * 0.125f;  // DH^-0.5
    }
    __syncthreads();
    if (t < 17) {
        float mx = -FLT_MAX;
        for (int j = 0; j < 17; j++) mx = fmaxf(mx, s[t][j]);
        float sum = 0.f;
        for (int j = 0; j < 17; j++) { float e = expf(s[t][j] - mx); s[t][j] = e; sum += e; }
        float inv = 1.f / sum;
        for (int j = 0; j < 17; j++) s[t][j] *= inv;
    }
    __syncthreads();
    for (int idx = t; idx < 17 * 64; idx += 128) {
        int n = idx >> 6, d = idx & 63;
        float a = 0.f;
#pragma unroll
        for (int j = 0; j < 17; j++) a = fmaf(s[n][j], vv[j][d], a);
        g_o[(size_t)(b * 17 + n) * 512 + h * 64 + d] = a;
    }
}

// ---------------- host ------------------------------------------------------
extern "C" void kernel_launch(void* const* d_in, const int* in_sizes, int n_in,
                              void* d_out, int out_size)
{
    (void)in_sizes; (void)n_in; (void)out_size;
    const float* img     = (const float*)d_in[0];
    const float* conv1_w = (const float*)d_in[1];
    const float* conv2_w = (const float*)d_in[2];
    const float* conv3_w = (const float*)d_in[3];
    const float* flat_w  = (const float*)d_in[4];
    const float* flat_b  = (const float*)d_in[5];
    const float* cls_tok = (const float*)d_in[6];
    const float* pos_emb = (const float*)d_in[7];
    const float* ln1_g   = (const float*)d_in[8];
    const float* ln1_b   = (const float*)d_in[9];
    const float* qkv_w   = (const float*)d_in[10];
    const float* out_w   = (const float*)d_in[11];
    const float* out_b   = (const float*)d_in[12];
    const float* ln2_g   = (const float*)d_in[13];
    const float* ln2_b   = (const float*)d_in[14];
    const float* ff1_w   = (const float*)d_in[15];
    const float* ff1_b   = (const float*)d_in[16];
    const float* ff2_w   = (const float*)d_in[17];
    const float* ff2_b   = (const float*)d_in[18];
    const float* hln_g   = (const float*)d_in[19];
    const float* hln_b   = (const float*)d_in[20];
    const float* head_w  = (const float*)d_in[21];
    const float* head_b  = (const float*)d_in[22];
    float* out = (float*)d_out;

    float *p_patches, *p_c1, *p_t1, *p_p1, *p_c2, *p_t2, *p_p2, *p_c3, *p_t3, *p_p3;
    float *p_tok, *p_x, *p_h, *p_qkv, *p_o, *p_ff, *p_cls;
    cudaGetSymbolAddress((void**)&p_patches, g_patches);
    cudaGetSymbolAddress((void**)&p_c1, g_c1);
    cudaGetSymbolAddress((void**)&p_t1, g_t1);
    cudaGetSymbolAddress((void**)&p_p1, g_p1);
    cudaGetSymbolAddress((void**)&p_c2, g_c2);
    cudaGetSymbolAddress((void**)&p_t2, g_t2);
    cudaGetSymbolAddress((void**)&p_p2, g_p2);
    cudaGetSymbolAddress((void**)&p_c3, g_c3);
    cudaGetSymbolAddress((void**)&p_t3, g_t3);
    cudaGetSymbolAddress((void**)&p_p3, g_p3);
    cudaGetSymbolAddress((void**)&p_tok, g_tok);
    cudaGetSymbolAddress((void**)&p_x,   g_x);
    cudaGetSymbolAddress((void**)&p_h,   g_h);
    cudaGetSymbolAddress((void**)&p_qkv, g_qkv);
    cudaGetSymbolAddress((void**)&p_o,   g_o);
    cudaGetSymbolAddress((void**)&p_ff,  g_ff);
    cudaGetSymbolAddress((void**)&p_cls, g_cls);

    // ---- CNN ----
    extract_patches_kernel<<<(NPATCH * 220 * 220 + 255) / 256, 256>>>(img);

    conv7s2_relu_kernel<1, 32, 220, 220, 107, 107><<<dim3(NPATCH, 14 * 14), 128>>>(p_patches, conv1_w, p_c1);
    pool_cols_kernel<107, 103><<<(NPATCH * 32 * 107 * 103 + 255) / 256, 256>>>(p_c1, p_t1, NPATCH * 32 * 107);
    pool_rows_kernel<107, 103, 103><<<(NPATCH * 32 * 103 * 103 + 255) / 256, 256>>>(p_t1, p_p1, NPATCH * 32);

    conv7s2_relu_kernel<32, 64, 103, 103, 49, 49><<<dim3(NPATCH, 7 * 7), 256>>>(p_p1, conv2_w, p_c2);
    pool_cols_kernel<49, 45><<<(NPATCH * 64 * 49 * 45 + 255) / 256, 256>>>(p_c2, p_t2, NPATCH * 64 * 49);
    pool_rows_kernel<49, 45, 45><<<(NPATCH * 64 * 45 * 45 + 255) / 256, 256>>>(p_t2, p_p2, NPATCH * 64);

    conv7s2_relu_kernel<64, 64, 45, 45, 20, 20><<<dim3(NPATCH, 3 * 3), 256>>>(p_p2, conv3_w, p_c3);
    pool_cols_kernel<20, 16><<<(NPATCH * 64 * 20 * 16 + 255) / 256, 256>>>(p_c3, p_t3, NPATCH * 64 * 20);
    pool_rows_kernel<20, 16, 16><<<(NPATCH * 64 * 16 * 16 + 255) / 256, 256>>>(p_t3, p_p3, NPATCH * 64);

    // ---- flatten linear: feat[256,16384] @ flat_w[16384,512] + flat_b ----
    gemm_kernel<0><<<dim3(512 / 64, (NPATCH + 31) / 32), 256>>>(p_p3, flat_w, flat_b, nullptr, p_tok,
                                                                NPATCH, 512, 16384);
    embed_kernel<<<(ROWS * 512 + 255) / 256, 256>>>(cls_tok, pos_emb);

    // ---- transformer layers ----
    for (int L = 0; L < 6; L++) {
        ln_kernel<<<ROWS, 128>>>(p_x, ln1_g + L * 512, ln1_b + L * 512, p_h, 512);
        gemm_kernel<0><<<dim3(1536 / 64, (ROWS + 31) / 32), 256>>>(p_h, qkv_w + (size_t)L * 512 * 1536,
                                                                   nullptr, nullptr, p_qkv, ROWS, 1536, 512);
        attn_kernel<<<128, 128>>>();
        gemm_kernel<0><<<dim3(512 / 64, (ROWS + 31) / 32), 256>>>(p_o, out_w + (size_t)L * 512 * 512,
                                                                  out_b + L * 512, p_x, p_x, ROWS, 512, 512);
        ln_kernel<<<ROWS, 128>>>(p_x, ln2_g + L * 512, ln2_b + L * 512, p_h, 512);
        gemm_kernel<1><<<dim3(2048 / 64, (ROWS + 31) / 32), 256>>>(p_h, ff1_w + (size_t)L * 512 * 2048,
                                                                   ff1_b + L * 2048, nullptr, p_ff, ROWS, 2048, 512);
        gemm_kernel<0><<<dim3(512 / 64, (ROWS + 31) / 32), 256>>>(p_ff, ff2_w + (size_t)L * 2048 * 512,
                                                                  ff2_b + L * 512, p_x, p_x, ROWS, 512, 2048);
    }

    // ---- head ----
    ln_kernel<<<16, 128>>>(p_x, hln_g, hln_b, p_cls, 17 * 512);
    gemm_kernel<0><<<dim3((1000 + 63) / 64, 1), 256>>>(p_cls, head_w, head_b, nullptr, out, 16, 1000, 512);
}

// round 4
// speedup vs baseline: 1.1816x; 1.1816x over previous
#include <cuda_runtime.h>
#include <math.h>
#include <float.h>

// ============================================================================
// HybridViT forward, round 3: fp32 convs with 8oc x PX register tiles,
// fused separable maxpools, patch extraction folded into conv1,
// split-K flat GEMM. Transformer path unchanged (known correct).
// ============================================================================

#define NPATCH 256      // B*NP = 16*16
#define ROWS   272      // B*(NP+1) = 16*17

// ---------------- scratch (device globals; allocation-free rule) ------------
__device__ float g_c1[(size_t)NPATCH*32*107*107];
__device__ float g_p1[(size_t)NPATCH*32*103*103];
__device__ float g_c2[(size_t)NPATCH*64*49*49];
__device__ float g_p2[(size_t)NPATCH*64*45*45];
__device__ float g_c3[(size_t)NPATCH*64*20*20];
__device__ float g_p3[(size_t)NPATCH*64*16*16];   // == feat [256, 16384]
__device__ float g_fpart[(size_t)8*NPATCH*512];
__device__ float g_tok[(size_t)NPATCH*512];
__device__ float g_x  [(size_t)ROWS*512];
__device__ float g_h  [(size_t)ROWS*512];
__device__ float g_qkv[(size_t)ROWS*1536];
__device__ float g_o  [(size_t)ROWS*512];
__device__ float g_ff [(size_t)ROWS*2048];
__device__ float g_cls[(size_t)16*512];

// ---------------- direct conv 7x7 stride 2 VALID + ReLU, v2 ----------------
// Per thread: 8 output channels x PX consecutive x-positions.
// s_w transposed to [k][oc] (stride 72) -> conflict-free float4 weight reads.
// Input via float2: one load serves kw and kw+1 taps.
template<bool FROM_IMG, int IC, int OC, int IN_H, int IN_W, int OUT_H, int OUT_W,
         int TH, int PX, int NT>
__global__ __launch_bounds__(NT) void conv7s2_v2(const float* __restrict__ in,
                                                 const float* __restrict__ w,
                                                 float* __restrict__ out)
{
    constexpr int ITH  = (TH - 1) * 2 + 7;
    constexpr int SW   = ((IN_W + 1) & ~1);          // even smem row stride
    constexpr int CX   = (OUT_W + PX - 1) / PX;
    constexpr int OCG  = OC / 8;
    constexpr int PG   = TH * CX;
    constexpr int ACTIVE = PG * OCG;
    constexpr int WSTR = 72;
    __shared__ __align__(16) float s_w[49 * WSTR];
    __shared__ __align__(16) float s_in[ITH * SW + 16];

    const int patch = blockIdx.x;
    const int strip = blockIdx.y;
    const int t   = threadIdx.x;
    const int ocg = t % OCG;
    const int pg  = t / OCG;
    const int row = pg / CX;
    const int chunk = pg % CX;
    const int oc0 = ocg * 8;
    const int x0  = chunk * PX;
    const int oy  = strip * TH + row;
    const int iy0 = strip * TH * 2;

    size_t img_base = 0;
    if (FROM_IMG) {
        int b = patch >> 4, gh = (patch >> 2) & 3, gw = patch & 3;
        img_base = ((size_t)(b * 880 + gh * 220)) * 880 + gw * 220;
    }

    float acc[8][PX];
#pragma unroll
    for (int i = 0; i < 8; i++)
#pragma unroll
        for (int j = 0; j < PX; j++) acc[i][j] = 0.f;

    for (int ci = 0; ci < IC; ci++) {
        __syncthreads();
        // weights -> s_w[k*WSTR + oc]
        for (int idx = t; idx < OC * 49; idx += NT) {
            int oc = idx / 49, k = idx - oc * 49;
            s_w[k * WSTR + oc] = w[((size_t)oc * IC + ci) * 49 + k];
        }
        // input rows [iy0, iy0+ITH)
        if (FROM_IMG) {
            for (int idx = t; idx < ITH * IN_W; idx += NT) {
                int ly = idx / IN_W, lx = idx - ly * IN_W;
                int iy = iy0 + ly;
                s_in[ly * SW + lx] = (iy < IN_H) ? in[img_base + (size_t)iy * 880 + lx] : 0.f;
            }
        } else {
            const float* ic_ptr = in + ((size_t)patch * IC + ci) * IN_H * IN_W;
            for (int idx = t; idx < ITH * IN_W; idx += NT) {
                int ly = idx / IN_W, lx = idx - ly * IN_W;
                int iy = iy0 + ly;
                s_in[ly * SW + lx] = (iy < IN_H) ? ic_ptr[(size_t)iy * IN_W + lx] : 0.f;
            }
        }
        __syncthreads();

        if (t < ACTIVE) {
#pragma unroll 1
            for (int kh = 0; kh < 7; kh++) {
                const float* rbase = &s_in[(row * 2 + kh) * SW + x0 * 2];
#pragma unroll
                for (int kw = 0; kw < 7; kw += 2) {
                    float2 v2[PX];
#pragma unroll
                    for (int j = 0; j < PX; j++)
                        v2[j] = *(const float2*)(rbase + 2 * j + kw);
                    {
                        const int k = kh * 7 + kw;
                        const float4 wa = *(const float4*)&s_w[k * WSTR + oc0];
                        const float4 wb = *(const float4*)&s_w[k * WSTR + oc0 + 4];
                        const float wv[8] = {wa.x, wa.y, wa.z, wa.w, wb.x, wb.y, wb.z, wb.w};
#pragma unroll
                        for (int i = 0; i < 8; i++)
#pragma unroll
                            for (int j = 0; j < PX; j++)
                                acc[i][j] = fmaf(wv[i], v2[j].x, acc[i][j]);
                    }
                    if (kw + 1 < 7) {
                        const int k = kh * 7 + kw + 1;
                        const float4 wa = *(const float4*)&s_w[k * WSTR + oc0];
                        const float4 wb = *(const float4*)&s_w[k * WSTR + oc0 + 4];
                        const float wv[8] = {wa.x, wa.y, wa.z, wa.w, wb.x, wb.y, wb.z, wb.w};
#pragma unroll
                        for (int i = 0; i < 8; i++)
#pragma unroll
                            for (int j = 0; j < PX; j++)
                                acc[i][j] = fmaf(wv[i], v2[j].y, acc[i][j]);
                    }
                }
            }
        }
    }

    if (t < ACTIVE && oy < OUT_H) {
#pragma unroll
        for (int i = 0; i < 8; i++) {
            float* op = out + (((size_t)patch * OC + oc0 + i) * OUT_H + oy) * OUT_W;
#pragma unroll
            for (int j = 0; j < PX; j++) {
                int ox = x0 + j;
                if (ox < OUT_W) op[ox] = fmaxf(acc[i][j], 0.f);
            }
        }
    }
}

// ---------------- fused separable maxpool 7x7 s1 p1 (out = in - 4) ----------
// Whole-plane version (stages 2 and 3).
template<int IN_HW, int NT>
__global__ __launch_bounds__(NT) void pool_plane_kernel(const float* __restrict__ in,
                                                        float* __restrict__ out)
{
    constexpr int OUT = IN_HW - 4;
    __shared__ float s_raw[IN_HW * IN_HW];
    __shared__ float s_col[IN_HW * OUT];
    const size_t plane = blockIdx.x;
    const float* ip = in + plane * IN_HW * IN_HW;
    for (int idx = threadIdx.x; idx < IN_HW * IN_HW; idx += NT) s_raw[idx] = ip[idx];
    __syncthreads();
    for (int idx = threadIdx.x; idx < IN_HW * OUT; idx += NT) {
        int r = idx / OUT, ox = idx - r * OUT;
        int lo = max(ox - 1, 0), hi = min(ox + 5, IN_HW - 1);
        float m = -FLT_MAX;
        for (int x = lo; x <= hi; x++) m = fmaxf(m, s_raw[r * IN_HW + x]);
        s_col[r * OUT + ox] = m;
    }
    __syncthreads();
    float* op = out + plane * OUT * OUT;
    for (int idx = threadIdx.x; idx < OUT * OUT; idx += NT) {
        int oyy = idx / OUT, ox = idx - oyy * OUT;
        int lo = max(oyy - 1, 0), hi = min(oyy + 5, IN_HW - 1);
        float m = -FLT_MAX;
        for (int y = lo; y <= hi; y++) m = fmaxf(m, s_col[y * OUT + ox]);
        op[idx] = m;
    }
}

// Row-strip version (stage 1: 107x107 plane too big for one smem tile).
template<int IN_H, int IN_W, int TH, int NT>
__global__ __launch_bounds__(NT) void pool_strip_kernel(const float* __restrict__ in,
                                                        float* __restrict__ out)
{
    constexpr int OUT_W = IN_W - 4;
    constexpr int OUT_H = IN_H - 4;
    constexpr int MAXR  = TH + 6;
    __shared__ float s_raw[MAXR * IN_W];
    __shared__ float s_col[MAXR * OUT_W];
    const size_t plane = blockIdx.x;
    const int r0    = blockIdx.y * TH;
    const int lbase = max(r0 - 1, 0);
    const int lend  = min(r0 + TH + 4, IN_H - 1);
    const int nrows = lend - lbase + 1;
    const float* ip = in + plane * IN_H * IN_W;
    for (int idx = threadIdx.x; idx < nrows * IN_W; idx += NT)
        s_raw[idx] = ip[(size_t)lbase * IN_W + idx];
    __syncthreads();
    for (int idx = threadIdx.x; idx < nrows * OUT_W; idx += NT) {
        int r = idx / OUT_W, ox = idx - r * OUT_W;
        int lo = max(ox - 1, 0), hi = min(ox + 5, IN_W - 1);
        float m = -FLT_MAX;
        for (int x = lo; x <= hi; x++) m = fmaxf(m, s_raw[r * IN_W + x]);
        s_col[r * OUT_W + ox] = m;
    }
    __syncthreads();
    float* op = out + plane * OUT_H * OUT_W;
    for (int idx = threadIdx.x; idx < TH * OUT_W; idx += NT) {
        int orow = idx / OUT_W, ox = idx - orow * OUT_W;
        int oyy = r0 + orow;
        if (oyy >= OUT_H) continue;
        int glo = max(oyy - 1, 0), ghi = min(oyy + 5, IN_H - 1);
        float m = -FLT_MAX;
        for (int y = glo; y <= ghi; y++) m = fmaxf(m, s_col[(y - lbase) * OUT_W + ox]);
        op[(size_t)oyy * OUT_W + ox] = m;
    }
}

// ---------------- tiled SGEMM: C = act(A@B + bias) + res --------------------
__device__ __forceinline__ float gelu_f(float x)
{
    return 0.5f * x * (1.0f + erff(x * 0.7071067811865476f));
}

template<int ACT>   // 0 = none, 1 = exact GELU (applied before residual)
__global__ void gemm_kernel(const float* __restrict__ A, const float* __restrict__ Bm,
                            const float* __restrict__ bias, const float* __restrict__ res,
                            float* __restrict__ C, int M, int N, int K)
{
    __shared__ float sA[16][33];
    __shared__ float sB[16][64];
    const int bm = blockIdx.y * 32;
    const int bn = blockIdx.x * 64;
    const int t  = threadIdx.x;          // 256
    const int tm = (t >> 4) << 1;
    const int tn = (t & 15) << 2;
    float acc[2][4] = {{0, 0, 0, 0}, {0, 0, 0, 0}};
    for (int k0 = 0; k0 < K; k0 += 16) {
#pragma unroll
        for (int i = 0; i < 2; i++) {
            int e = t * 2 + i, m = e >> 4, kk = e & 15;
            sA[kk][m] = (bm + m < M) ? A[(size_t)(bm + m) * K + k0 + kk] : 0.f;
        }
#pragma unroll
        for (int i = 0; i < 4; i++) {
            int e = t * 4 + i, kk = e >> 6, n = e & 63;
            sB[kk][n] = (bn + n < N) ? Bm[(size_t)(k0 + kk) * N + bn + n] : 0.f;
        }
        __syncthreads();
#pragma unroll
        for (int kk = 0; kk < 16; kk++) {
            float a0 = sA[kk][tm], a1 = sA[kk][tm + 1];
            float b0 = sB[kk][tn + 0], b1 = sB[kk][tn + 1];
            float b2 = sB[kk][tn + 2], b3 = sB[kk][tn + 3];
            acc[0][0] = fmaf(a0, b0, acc[0][0]); acc[0][1] = fmaf(a0, b1, acc[0][1]);
            acc[0][2] = fmaf(a0, b2, acc[0][2]); acc[0][3] = fmaf(a0, b3, acc[0][3]);
            acc[1][0] = fmaf(a1, b0, acc[1][0]); acc[1][1] = fmaf(a1, b1, acc[1][1]);
            acc[1][2] = fmaf(a1, b2, acc[1][2]); acc[1][3] = fmaf(a1, b3, acc[1][3]);
        }
        __syncthreads();
    }
#pragma unroll
    for (int i = 0; i < 2; i++) {
        int m = bm + tm + i;
        if (m >= M) continue;
#pragma unroll
        for (int j = 0; j < 4; j++) {
            int n = bn + tn + j;
            if (n >= N) continue;
            float v = acc[i][j];
            if (bias) v += bias[n];
            if (ACT == 1) v = gelu_f(v);
            if (res) v += res[(size_t)m * N + n];
            C[(size_t)m * N + n] = v;
        }
    }
}

// ---------------- split-K GEMM (no bias/act); writes per-z partial slab -----
__global__ void gemm_splitk_kernel(const float* __restrict__ A, const float* __restrict__ Bm,
                                   float* __restrict__ Cpart, int M, int N, int K, int KC)
{
    __shared__ float sA[16][33];
    __shared__ float sB[16][64];
    const int bm = blockIdx.y * 32;
    const int bn = blockIdx.x * 64;
    const int z  = blockIdx.z;
    const int t  = threadIdx.x;
    const int tm = (t >> 4) << 1;
    const int tn = (t & 15) << 2;
    float acc[2][4] = {{0, 0, 0, 0}, {0, 0, 0, 0}};
    const int kend = z * KC + KC;
    for (int k0 = z * KC; k0 < kend; k0 += 16) {
#pragma unroll
        for (int i = 0; i < 2; i++) {
            int e = t * 2 + i, m = e >> 4, kk = e & 15;
            sA[kk][m] = (bm + m < M) ? A[(size_t)(bm + m) * K + k0 + kk] : 0.f;
        }
#pragma unroll
        for (int i = 0; i < 4; i++) {
            int e = t * 4 + i, kk = e >> 6, n = e & 63;
            sB[kk][n] = (bn + n < N) ? Bm[(size_t)(k0 + kk) * N + bn + n] : 0.f;
        }
        __syncthreads();
#pragma unroll
        for (int kk = 0; kk < 16; kk++) {
            float a0 = sA[kk][tm], a1 = sA[kk][tm + 1];
            float b0 = sB[kk][tn + 0], b1 = sB[kk][tn + 1];
            float b2 = sB[kk][tn + 2], b3 = sB[kk][tn + 3];
            acc[0][0] = fmaf(a0, b0, acc[0][0]); acc[0][1] = fmaf(a0, b1, acc[0][1]);
            acc[0][2] = fmaf(a0, b2, acc[0][2]); acc[0][3] = fmaf(a0, b3, acc[0][3]);
            acc[1][0] = fmaf(a1, b0, acc[1][0]); acc[1][1] = fmaf(a1, b1, acc[1][1]);
            acc[1][2] = fmaf(a1, b2, acc[1][2]); acc[1][3] = fmaf(a1, b3, acc[1][3]);
        }
        __syncthreads();
    }
    float* Cs = Cpart + (size_t)z * M * N;
#pragma unroll
    for (int i = 0; i < 2; i++) {
        int m = bm + tm + i;
        if (m >= M) continue;
#pragma unroll
        for (int j = 0; j < 4; j++) {
            int n = bn + tn + j;
            if (n >= N) continue;
            Cs[(size_t)m * N + n] = acc[i][j];
        }
    }
}

__global__ void flat_reduce_kernel(const float* __restrict__ part, const float* __restrict__ bias,
                                   float* __restrict__ outp, int M, int N, int S)
{
    int idx = blockIdx.x * blockDim.x + threadIdx.x;
    if (idx >= M * N) return;
    float v = bias[idx % N];
    for (int s = 0; s < S; s++) v += part[(size_t)s * M * N + idx];
    outp[idx] = v;
}

// ---------------- LayerNorm over 512 ----------------------------------------
__global__ void ln_kernel(const float* __restrict__ x, const float* __restrict__ g,
                          const float* __restrict__ bb, float* __restrict__ out,
                          int row_stride)
{
    const int row = blockIdx.x;
    const float* xr = x + (size_t)row * row_stride;
    float* orow = out + (size_t)row * 512;
    const int t = threadIdx.x; // 128
    float v[4], s = 0.f, s2 = 0.f;
#pragma unroll
    for (int i = 0; i < 4; i++) { v[i] = xr[i * 128 + t]; s += v[i]; s2 += v[i] * v[i]; }
#pragma unroll
    for (int o = 16; o; o >>= 1) {
        s  += __shfl_xor_sync(0xffffffffu, s,  o);
        s2 += __shfl_xor_sync(0xffffffffu, s2, o);
    }
    __shared__ float rs[4], rs2[4];
    if ((t & 31) == 0) { rs[t >> 5] = s; rs2[t >> 5] = s2; }
    __syncthreads();
    float tot  = rs[0] + rs[1] + rs[2] + rs[3];
    float tot2 = rs2[0] + rs2[1] + rs2[2] + rs2[3];
    float mean = tot  * (1.f / 512.f);
    float var  = tot2 * (1.f / 512.f) - mean * mean;
    float rstd = rsqrtf(var + 1e-5f);
#pragma unroll
    for (int i = 0; i < 4; i++) {
        int c = i * 128 + t;
        orow[c] = (v[i] - mean) * rstd * g[c] + bb[c];
    }
}

// ---------------- token assembly: cls + tokens + pos ------------------------
__global__ void embed_kernel(const float* __restrict__ cls_token, const float* __restrict__ pos_emb)
{
    int idx = blockIdx.x * blockDim.x + threadIdx.x;
    if (idx >= ROWS * 512) return;
    int row = idx >> 9, c = idx & 511;
    int b = row / 17, n = row - b * 17;
    float v = (n == 0) ? cls_token[c] : g_tok[(size_t)(b * 16 + n - 1) * 512 + c];
    g_x[idx] = v + pos_emb[n * 512 + c];
}

// ---------------- attention: one block per (b, h), N=17, DH=64 --------------
__global__ void attn_kernel()
{
    const int bh = blockIdx.x;
    const int b = bh >> 3, h = bh & 7;
    __shared__ float q[17][64], kk[17][64], vv[17][64], s[17][17];
    const int t = threadIdx.x; // 128
    for (int idx = t; idx < 17 * 64; idx += 128) {
        int n = idx >> 6, d = idx & 63;
        const float* base = g_qkv + (size_t)(b * 17 + n) * 1536 + h * 64 + d;
        q[n][d]  = base[0];
        kk[n][d] = base[512];
        vv[n][d] = base[1024];
    }
    __syncthreads();
    for (int idx = t; idx < 289; idx += 128) {
        int i = idx / 17, j = idx - i * 17;
        float a = 0.f;
#pragma unroll
        for (int d = 0; d < 64; d++) a = fmaf(q[i][d], kk[j][d], a);
        s[i][j] = a * 0.125f;
    }
    __syncthreads();
    if (t < 17) {
        float mx = -FLT_MAX;
        for (int j = 0; j < 17; j++) mx = fmaxf(mx, s[t][j]);
        float sum = 0.f;
        for (int j = 0; j < 17; j++) { float e = expf(s[t][j] - mx); s[t][j] = e; sum += e; }
        float inv = 1.f / sum;
        for (int j = 0; j < 17; j++) s[t][j] *= inv;
    }
    __syncthreads();
    for (int idx = t; idx < 17 * 64; idx += 128) {
        int n = idx >> 6, d = idx & 63;
        float a = 0.f;
#pragma unroll
        for (int j = 0; j < 17; j++) a = fmaf(s[n][j], vv[j][d], a);
        g_o[(size_t)(b * 17 + n) * 512 + h * 64 + d] = a;
    }
}

// ---------------- host ------------------------------------------------------
extern "C" void kernel_launch(void* const* d_in, const int* in_sizes, int n_in,
                              void* d_out, int out_size)
{
    (void)in_sizes; (void)n_in; (void)out_size;
    const float* img     = (const float*)d_in[0];
    const float* conv1_w = (const float*)d_in[1];
    const float* conv2_w = (const float*)d_in[2];
    const float* conv3_w = (const float*)d_in[3];
    const float* flat_w  = (const float*)d_in[4];
    const float* flat_b  = (const float*)d_in[5];
    const float* cls_tok = (const float*)d_in[6];
    const float* pos_emb = (const float*)d_in[7];
    const float* ln1_g   = (const float*)d_in[8];
    const float* ln1_b   = (const float*)d_in[9];
    const float* qkv_w   = (const float*)d_in[10];
    const float* out_w   = (const float*)d_in[11];
    const float* out_b   = (const float*)d_in[12];
    const float* ln2_g   = (const float*)d_in[13];
    const float* ln2_b   = (const float*)d_in[14];
    const float* ff1_w   = (const float*)d_in[15];
    const float* ff1_b   = (const float*)d_in[16];
    const float* ff2_w   = (const float*)d_in[17];
    const float* ff2_b   = (const float*)d_in[18];
    const float* hln_g   = (const float*)d_in[19];
    const float* hln_b   = (const float*)d_in[20];
    const float* head_w  = (const float*)d_in[21];
    const float* head_b  = (const float*)d_in[22];
    float* out = (float*)d_out;

    float *p_c1, *p_p1, *p_c2, *p_p2, *p_c3, *p_p3;
    float *p_fpart, *p_tok, *p_x, *p_h, *p_qkv, *p_o, *p_ff, *p_cls;
    cudaGetSymbolAddress((void**)&p_c1, g_c1);
    cudaGetSymbolAddress((void**)&p_p1, g_p1);
    cudaGetSymbolAddress((void**)&p_c2, g_c2);
    cudaGetSymbolAddress((void**)&p_p2, g_p2);
    cudaGetSymbolAddress((void**)&p_c3, g_c3);
    cudaGetSymbolAddress((void**)&p_p3, g_p3);
    cudaGetSymbolAddress((void**)&p_fpart, g_fpart);
    cudaGetSymbolAddress((void**)&p_tok, g_tok);
    cudaGetSymbolAddress((void**)&p_x,   g_x);
    cudaGetSymbolAddress((void**)&p_h,   g_h);
    cudaGetSymbolAddress((void**)&p_qkv, g_qkv);
    cudaGetSymbolAddress((void**)&p_o,   g_o);
    cudaGetSymbolAddress((void**)&p_ff,  g_ff);
    cudaGetSymbolAddress((void**)&p_cls, g_cls);

    // ---- CNN ----
    // conv1: img -> c1 [256,32,107,107]; patch extraction folded in.
    conv7s2_v2<true, 1, 32, 220, 220, 107, 107, 4, 8, 224>
        <<<dim3(NPATCH, 27), 224>>>(img, conv1_w, p_c1);
    // pool1: 107x107 -> 103x103 (strip-fused separable)
    pool_strip_kernel<107, 107, 26, 256><<<dim3(NPATCH * 32, 4), 256>>>(p_c1, p_p1);

    // conv2: p1 -> c2 [256,64,49,49]
    conv7s2_v2<false, 32, 64, 103, 103, 49, 49, 7, 7, 416>
        <<<dim3(NPATCH, 7), 416>>>(p_p1, conv2_w, p_c2);
    // pool2: 49x49 -> 45x45
    pool_plane_kernel<49, 256><<<NPATCH * 64, 256>>>(p_c2, p_p2);

    // conv3: p2 -> c3 [256,64,20,20]
    conv7s2_v2<false, 64, 64, 45, 45, 20, 20, 4, 5, 128>
        <<<dim3(NPATCH, 5), 128>>>(p_p2, conv3_w, p_c3);
    // pool3: 20x20 -> 16x16
    pool_plane_kernel<20, 128><<<NPATCH * 64, 128>>>(p_c3, p_p3);

    // ---- flatten linear (split-K=8): feat[256,16384] @ flat_w[16384,512] ----
    gemm_splitk_kernel<<<dim3(512 / 64, NPATCH / 32, 8), 256>>>(p_p3, flat_w, p_fpart,
                                                                NPATCH, 512, 16384, 2048);
    flat_reduce_kernel<<<(NPATCH * 512 + 255) / 256, 256>>>(p_fpart, flat_b, p_tok,
                                                            NPATCH, 512, 8);
    embed_kernel<<<(ROWS * 512 + 255) / 256, 256>>>(cls_tok, pos_emb);

    // ---- transformer layers ----
    for (int L = 0; L < 6; L++) {
        ln_kernel<<<ROWS, 128>>>(p_x, ln1_g + L * 512, ln1_b + L * 512, p_h, 512);
        gemm_kernel<0><<<dim3(1536 / 64, (ROWS + 31) / 32), 256>>>(p_h, qkv_w + (size_t)L * 512 * 1536,
                                                                   nullptr, nullptr, p_qkv, ROWS, 1536, 512);
        attn_kernel<<<128, 128>>>();
        gemm_kernel<0><<<dim3(512 / 64, (ROWS + 31) / 32), 256>>>(p_o, out_w + (size_t)L * 512 * 512,
                                                                  out_b + L * 512, p_x, p_x, ROWS, 512, 512);
        ln_kernel<<<ROWS, 128>>>(p_x, ln2_g + L * 512, ln2_b + L * 512, p_h, 512);
        gemm_kernel<1><<<dim3(2048 / 64, (ROWS + 31) / 32), 256>>>(p_h, ff1_w + (size_t)L * 512 * 2048,
                                                                   ff1_b + L * 2048, nullptr, p_ff, ROWS, 2048, 512);
        gemm_kernel<0><<<dim3(512 / 64, (ROWS + 31) / 32), 256>>>(p_ff, ff2_w + (size_t)L * 2048 * 512,
                                                                  ff2_b + L * 512, p_x, p_x, ROWS, 512, 2048);
    }

    // ---- head ----
    ln_kernel<<<16, 128>>>(p_x, hln_g, hln_b, p_cls, 17 * 512);
    gemm_kernel<0><<<dim3((1000 + 63) / 64, 1), 256>>>(p_cls, head_w, head_b, nullptr, out, 16, 1000, 512);
}